// round 11
// baseline (speedup 1.0000x reference)
#include <cuda_runtime.h>
#include <cuda_bf16.h>

typedef unsigned long long ULL;

#define HW 784
#define NPIX 3136

// ---------------------------------------------------------------------------
// accd layout (doubles): ds_sum@0, ds_ss@256, bn2_sum@512, bn2_ss@576,
// bn3_sum@640, bn3_ss@896, bn1_sum@1152, bn1_ss@1216.
// KL partial slots: kp_*[t*40 + lb]  (blocks per tensor: 32/8/36/16).
// ---------------------------------------------------------------------------
struct __align__(16) Scratch {
    float f_ds[32768], f_c1[8192], f_c2[36864], f_c3[16384];
    float kp_ef[160], kp_el[160], kp_spl[160];
    double accd[1280];
    float buf_ds[802816], buf_c3[802816];
    float buf_c1[200704], buf_peg[200704], buf_c2[200704];
};
__device__ Scratch g_s;

// ---------------- helpers --------------------------------------------------
__device__ __forceinline__ ULL addf2(ULL a, ULL b) {
    ULL r; asm("add.rn.f32x2 %0,%1,%2;" : "=l"(r) : "l"(a), "l"(b)); return r;
}
__device__ __forceinline__ ULL pack2(float v) {
    ULL r; unsigned u = __float_as_uint(v);
    asm("mov.b64 %0,{%1,%1};" : "=l"(r) : "r"(u)); return r;
}
__device__ __forceinline__ ULL packAB(float a, float b) {
    return ((ULL)__float_as_uint(b) << 32) | (ULL)__float_as_uint(a);
}
#define ABS2_MASK 0x7FFFFFFF7FFFFFFFULL

__device__ __forceinline__ float blk_sum(float v) {
    __shared__ float red[8];
    #pragma unroll
    for (int o = 16; o > 0; o >>= 1) v += __shfl_xor_sync(0xffffffffu, v, o);
    int w = threadIdx.x >> 5, l = threadIdx.x & 31;
    if (l == 0) red[w] = v;
    __syncthreads();
    if (w == 0) {
        float s = (l < 8) ? red[l] : 0.f;
        #pragma unroll
        for (int o = 4; o > 0; o >>= 1) s += __shfl_xor_sync(0xffffffffu, s, o);
        if (l == 0) red[0] = s;
    }
    __syncthreads();
    float r = red[0]; __syncthreads();
    return r;
}
__device__ __forceinline__ void blk_minmax(float mn, float mx, float* omn, float* omx) {
    __shared__ float rmn[8], rmx[8];
    #pragma unroll
    for (int o = 16; o > 0; o >>= 1) {
        mn = fminf(mn, __shfl_xor_sync(0xffffffffu, mn, o));
        mx = fmaxf(mx, __shfl_xor_sync(0xffffffffu, mx, o));
    }
    int w = threadIdx.x >> 5, l = threadIdx.x & 31;
    if (l == 0) { rmn[w] = mn; rmx[w] = mx; }
    __syncthreads();
    if (w == 0) {
        float a = (l < 8) ? rmn[l] : 3.4e38f;
        float b = (l < 8) ? rmx[l] : -3.4e38f;
        #pragma unroll
        for (int o = 4; o > 0; o >>= 1) {
            a = fminf(a, __shfl_xor_sync(0xffffffffu, a, o));
            b = fmaxf(b, __shfl_xor_sync(0xffffffffu, b, o));
        }
        if (l == 0) { rmn[0] = a; rmx[0] = b; }
    }
    __syncthreads();
    *omn = rmn[0]; *omx = rmx[0];
    __syncthreads();
}

// ---------------- recon: zero accd + per-tensor minmax + recon + KL parts --
__global__ void __launch_bounds__(256) recon_kernel(
    const float* __restrict__ w0, const float* __restrict__ w1,
    const float* __restrict__ w2, const float* __restrict__ w3,
    const float* __restrict__ a0, const float* __restrict__ a1,
    const float* __restrict__ a2, const float* __restrict__ a3,
    const float* __restrict__ l0, const float* __restrict__ l1,
    const float* __restrict__ l2, const float* __restrict__ l3)
{
    int bid = blockIdx.x, tid = threadIdx.x;
    if (bid == 0) {
        #pragma unroll
        for (int i = 0; i < 5; ++i) g_s.accd[i * 256 + tid] = 0.0;
    }
    int t, lb;
    if (bid < 32)      { t = 0; lb = bid; }
    else if (bid < 40) { t = 1; lb = bid - 32; }
    else if (bid < 76) { t = 2; lb = bid - 40; }
    else               { t = 3; lb = bid - 76; }
    const float *w, *aff, *lap; float* f; int n4;
    if (t == 0)      { w = w0; aff = a0; lap = l0; f = g_s.f_ds; n4 = 8192; }
    else if (t == 1) { w = w1; aff = a1; lap = l1; f = g_s.f_c1; n4 = 2048; }
    else if (t == 2) { w = w2; aff = a2; lap = l2; f = g_s.f_c2; n4 = 9216; }
    else             { w = w3; aff = a3; lap = l3; f = g_s.f_c3; n4 = 4096; }

    float mn = 3.4e38f, mx = -3.4e38f;
    for (int i = tid; i < n4; i += 256) {
        float4 v = ((const float4*)w)[i];
        mn = fminf(mn, fminf(fminf(v.x, v.y), fminf(v.z, v.w)));
        mx = fmaxf(mx, fmaxf(fmaxf(v.x, v.y), fmaxf(v.z, v.w)));
    }
    float wmin, wmax;
    blk_minmax(mn, mx, &wmin, &wmax);
    float range = wmax - wmin;

    int i4 = lb * 256 + tid;
    float4 v4 = ((const float4*)w)[i4];
    float4 l4 = ((const float4*)lap)[i4];
    float vv[4] = {v4.x, v4.y, v4.z, v4.w};
    float ll[4] = {l4.x, l4.y, l4.z, l4.w};
    float fo[4];
    float ef = 0.f, el = 0.f, spl = 0.f;
    #pragma unroll
    for (int k = 0; k < 4; ++k) {
        float v = vv[k];
        float tt = (v - wmin) / range;            // same FP sequence as ref
        int idx = (int)floorf(tt * 100.0f);
        float val = (idx < 100) ? v * aff[idx] : 0.0f;
        fo[k] = val;
        float e = expf(ll[k]);
        ef += expf(val);
        el += e;
        spl += e * (ll[k] - val);
    }
    ((float4*)f)[i4] = make_float4(fo[0], fo[1], fo[2], fo[3]);
    float sef  = blk_sum(ef);
    float sel  = blk_sum(el);
    float sspl = blk_sum(spl);
    if (tid == 0) {
        g_s.kp_ef[t * 40 + lb]  = sef;
        g_s.kp_el[t * 40 + lb]  = sel;
        g_s.kp_spl[t * 40 + lb] = sspl;
    }
}

// ---------------- 1x1 adder: 32px x 8og (og=warp), 4 outs/thread -----------
// FUSED: blockIdx.y<8 -> ds (stats), else c1 (no stats).
template<int CIN, bool FUSED, bool BN_IN, bool STATS_T>
__global__ void __launch_bounds__(256) adder1x1_kernel(
    const float* __restrict__ in, const float* __restrict__ wsrc_a,
    float* __restrict__ out_a, int Cout_a,
    const double* __restrict__ bsum, const double* __restrict__ bss,
    const float* __restrict__ bg, const float* __restrict__ bb,
    double* __restrict__ osum_a, double* __restrict__ oss_a)
{
    __shared__ __align__(16) ULL wq[16 * CIN];   // [og][c][pr(2)]
    __shared__ float scale[CIN], shift[CIN];
    int tid = threadIdx.x;
    int b = blockIdx.z, yb = blockIdx.y;

    const float* wsrc; float* out; int Cout, o0; bool do_stats;
    double *osum, *oss;
    if (FUSED) {
        bool is_ds = yb < 8;
        wsrc = is_ds ? g_s.f_ds : g_s.f_c1;
        out  = is_ds ? g_s.buf_ds : g_s.buf_c1;
        Cout = is_ds ? 256 : 64;
        o0   = (is_ds ? yb : yb - 8) * 32;
        do_stats = is_ds;
        osum = g_s.accd; oss = g_s.accd + 256;
    } else {
        wsrc = wsrc_a; out = out_a; Cout = Cout_a; o0 = yb * 32;
        do_stats = STATS_T; osum = osum_a; oss = oss_a;
    }
    int p0 = blockIdx.x * 32;

    for (int j = tid; j < 16 * CIN; j += 256) {
        int og = j / (2 * CIN), r = j - og * 2 * CIN;
        int c = r >> 1, pr = r & 1;
        int o = o0 + og * 4 + 2 * pr;
        wq[j] = packAB(-wsrc[o * CIN + c], -wsrc[(o + 1) * CIN + c]);
    }
    if (BN_IN) {
        if (tid < CIN) {
            double m = bsum[tid] * (1.0 / 3136.0);
            double var = bss[tid] * (1.0 / 3136.0) - m * m;
            float istd = rsqrtf((float)var + 1e-5f);
            float sc = istd * bg[tid];
            scale[tid] = sc;
            shift[tid] = bb[tid] - (float)m * sc;
        }
    }
    __syncthreads();

    int px = tid & 31, og = tid >> 5;       // og == warp id -> LDS broadcast
    int p = p0 + px;
    bool valid = p < HW;
    int pc = valid ? p : (HW - 1);

    const float* xp = in + (size_t)b * CIN * HW + pc;
    const ULL* wp = wq + og * 2 * CIN;
    ULL acc0 = 0, acc1 = 0;

    #pragma unroll 4
    for (int c = 0; c < CIN; ++c) {
        float xv = xp[(size_t)c * HW];
        if (BN_IN) xv = fmaxf(fmaf(xv, scale[c], shift[c]), 0.0f);
        ULL xx = pack2(xv);
        ulonglong2 ww = *(const ulonglong2*)(wp + c * 2);
        acc0 = addf2(acc0, addf2(xx, ww.x) & ABS2_MASK);
        acc1 = addf2(acc1, addf2(xx, ww.y) & ABS2_MASK);
    }

    float a[4];
    a[0] = __uint_as_float((unsigned)acc0); a[1] = __uint_as_float((unsigned)(acc0 >> 32));
    a[2] = __uint_as_float((unsigned)acc1); a[3] = __uint_as_float((unsigned)(acc1 >> 32));
    int ob = o0 + og * 4;
    if (valid) {
        #pragma unroll
        for (int k = 0; k < 4; ++k)
            out[((size_t)b * Cout + ob + k) * HW + p] = -a[k];
    }
    if (do_stats) {
        #pragma unroll
        for (int k = 0; k < 4; ++k) {
            float s  = valid ? -a[k] : 0.0f;
            float s2 = valid ? a[k] * a[k] : 0.0f;
            #pragma unroll
            for (int o = 16; o > 0; o >>= 1) {
                s  += __shfl_xor_sync(0xffffffffu, s,  o);
                s2 += __shfl_xor_sync(0xffffffffu, s2, o);
            }
            if (px == 0) {
                atomicAdd(&osum[ob + k], (double)s);
                atomicAdd(&oss[ob + k],  (double)s2);
            }
        }
    }
}

// ---------------- PEG depthwise 3x3: 512 blocks, half-plane + halo ---------
// block -> (b, ch, half): stages 16 rows (incl. halo), computes 14 rows.
__global__ void __launch_bounds__(256) peg_stage_kernel(
    const float* __restrict__ in, const float* __restrict__ pw,
    float* __restrict__ out, double* __restrict__ osum, double* __restrict__ oss)
{
    __shared__ __align__(16) float plane[16 * 28];   // rows y0-1 .. y0+14
    int tid = threadIdx.x;
    int b = blockIdx.x >> 7, r7 = blockIdx.x & 127;
    int ch = r7 >> 1, h = r7 & 1;
    int y0 = h * 14;
    const float* ip = in + ((size_t)(b * 64 + ch)) * HW;
    float* op = out + ((size_t)(b * 64 + ch)) * HW;

    // stage: 16 rows x 28 = 448 floats = 112 float4 (rows 16B-aligned)
    if (tid < 112) {
        int row = tid / 7, q = tid % 7;          // row-in-tile, quad-in-row
        int sy = y0 - 1 + row;
        if (sy >= 0 && sy < 28)
            ((float4*)plane)[tid] = ((const float4*)(ip + sy * 28))[q];
    }
    __syncthreads();

    float wc[9];
    #pragma unroll
    for (int t = 0; t < 9; ++t) wc[t] = pw[ch * 9 + t];

    float s = 0.f, s2 = 0.f;
    #pragma unroll
    for (int r = 0; r < 2; ++r) {
        int pl = tid + r * 256;                  // 0..391
        if (pl < 392) {
            int yl = pl / 28, xx = pl - yl * 28;
            int y = y0 + yl;
            float acc = 0.f;
            #pragma unroll
            for (int t = 0; t < 9; ++t) {
                int dy = t / 3 - 1, dx = t % 3 - 1;
                int yy = y + dy, xc = xx + dx;
                float v = (yy >= 0 && yy < 28 && xc >= 0 && xc < 28)
                          ? plane[(yl + 1 + dy) * 28 + xc] : 0.0f;
                acc += fabsf(v - wc[t]);
            }
            op[y * 28 + xx] = -acc;
            s += -acc;
            s2 += acc * acc;
        }
    }
    s = blk_sum(s); s2 = blk_sum(s2);
    if (tid == 0) {
        atomicAdd(&osum[ch], (double)s);
        atomicAdd(&oss[ch],  (double)s2);
    }
}

// ---------------- 3x3 adder: 32px x 8og, bn1 folded on input, bn2 stats ----
// grid (25, 4, 4) = 400 blocks; weight tile 16 outs, 36 KB.
__global__ void __launch_bounds__(256) adder3x3_kernel(
    const float* __restrict__ in, const float* __restrict__ wsrc,
    float* __restrict__ out,
    const double* __restrict__ bsum, const double* __restrict__ bss,
    const float* __restrict__ bg, const float* __restrict__ bb,
    double* __restrict__ osum, double* __restrict__ oss)
{
    __shared__ __align__(16) ULL wq[4608];   // [og][c*9+t], 36 KB
    __shared__ float scale[64], shift[64];
    int tid = threadIdx.x;
    int b = blockIdx.z, o0 = blockIdx.y * 16, p0 = blockIdx.x * 32;

    for (int j = tid; j < 4608; j += 256) {
        int og = j / 576, ct = j - og * 576;
        int o = o0 + og * 2;
        wq[j] = packAB(-wsrc[o * 576 + ct], -wsrc[(o + 1) * 576 + ct]);
    }
    if (tid < 64) {
        double m = bsum[tid] * (1.0 / 3136.0);
        double var = bss[tid] * (1.0 / 3136.0) - m * m;
        float istd = rsqrtf((float)var + 1e-5f);
        float sc = istd * bg[tid];
        scale[tid] = sc;
        shift[tid] = bb[tid] - (float)m * sc;
    }
    __syncthreads();

    int px = tid & 31, og = tid >> 5;       // og == warp -> LDS broadcast
    int p = p0 + px;
    bool valid = p < HW;
    int pc = valid ? p : (HW - 1);
    int y = pc / 28, x = pc - y * 28;

    int off[9]; bool vld[9];
    #pragma unroll
    for (int t = 0; t < 9; ++t) {
        int yy = y + t / 3 - 1, xx = x + t % 3 - 1;
        vld[t] = (yy >= 0 && yy < 28 && xx >= 0 && xx < 28);
        off[t] = yy * 28 + xx;
    }

    const ULL* wp = wq + og * 576;
    ULL acc0 = 0;

    for (int c = 0; c < 64; ++c) {
        const float* ip = in + ((size_t)(b * 64 + c)) * HW;
        float sc = scale[c], sh = shift[c];
        float v[9];
        #pragma unroll
        for (int t = 0; t < 9; ++t)
            v[t] = vld[t] ? fmaxf(fmaf(ip[off[t]], sc, sh), 0.0f) : 0.0f;
        const ULL* wc = wp + c * 9;
        #pragma unroll
        for (int t = 0; t < 9; ++t) {
            ULL xx2 = pack2(v[t]);
            acc0 = addf2(acc0, addf2(xx2, wc[t]) & ABS2_MASK);
        }
    }

    float a[2];
    a[0] = __uint_as_float((unsigned)acc0);
    a[1] = __uint_as_float((unsigned)(acc0 >> 32));
    int ob = o0 + og * 2;
    if (valid) {
        out[((size_t)b * 64 + ob) * HW + p]     = -a[0];
        out[((size_t)b * 64 + ob + 1) * HW + p] = -a[1];
    }
    #pragma unroll
    for (int k = 0; k < 2; ++k) {
        float s  = valid ? -a[k] : 0.0f;
        float s2 = valid ? a[k] * a[k] : 0.0f;
        #pragma unroll
        for (int o = 16; o > 0; o >>= 1) {
            s  += __shfl_xor_sync(0xffffffffu, s,  o);
            s2 += __shfl_xor_sync(0xffffffffu, s2, o);
        }
        if (px == 0) {
            atomicAdd(&osum[ob + k], (double)s);
            atomicAdd(&oss[ob + k],  (double)s2);
        }
    }
}

// ---------------- final: bn3/bnds + residual + relu + KL -------------------
__global__ void __launch_bounds__(256) final_kernel(
    const float* __restrict__ g3, const float* __restrict__ b3,
    const float* __restrict__ gds, const float* __restrict__ bds,
    float* __restrict__ out, int out_size)
{
    int idx4 = blockIdx.x * 256 + threadIdx.x;
    if (idx4 == 0 && out_size > 802816) {
        const float ns[4] = {32768.f, 8192.f, 36864.f, 16384.f};
        const int nb[4] = {32, 8, 36, 16};
        float kl = 0.f;
        #pragma unroll
        for (int t = 0; t < 4; ++t) {
            float ef = 0.f, el = 0.f, spl = 0.f;
            for (int lb = 0; lb < nb[t]; ++lb) {
                ef  += g_s.kp_ef[t * 40 + lb];
                el  += g_s.kp_el[t * 40 + lb];
                spl += g_s.kp_spl[t * 40 + lb];
            }
            kl += (spl / el + logf(ef) - logf(el)) / ns[t];
        }
        out[802816] = kl;
    }
    size_t base = (size_t)idx4 * 4;
    int ch = (int)((base / HW) & 255);

    double m3d = g_s.accd[640 + ch] * (1.0 / 3136.0);
    double v3d = g_s.accd[896 + ch] * (1.0 / 3136.0) - m3d * m3d;
    float m3 = (float)m3d, istd3 = rsqrtf((float)v3d + 1e-5f);
    float sc3 = istd3 * g3[ch], sh3 = b3[ch] - m3 * sc3;

    double mdd = g_s.accd[0 + ch] * (1.0 / 3136.0);
    double vdd = g_s.accd[256 + ch] * (1.0 / 3136.0) - mdd * mdd;
    float md = (float)mdd, istdd = rsqrtf((float)vdd + 1e-5f);
    float scd = istdd * gds[ch], shd = bds[ch] - md * scd;

    float4 a = *(const float4*)(g_s.buf_c3 + base);
    float4 d = *(const float4*)(g_s.buf_ds + base);
    float4 o;
    o.x = fmaxf(fmaf(a.x, sc3, sh3) + fmaxf(fmaf(d.x, scd, shd), 0.f), 0.f);
    o.y = fmaxf(fmaf(a.y, sc3, sh3) + fmaxf(fmaf(d.y, scd, shd), 0.f), 0.f);
    o.z = fmaxf(fmaf(a.z, sc3, sh3) + fmaxf(fmaf(d.z, scd, shd), 0.f), 0.f);
    o.w = fmaxf(fmaf(a.w, sc3, sh3) + fmaxf(fmaf(d.w, scd, shd), 0.f), 0.f);
    *(float4*)(out + base) = o;
}

// ---------------------------------------------------------------------------
extern "C" void kernel_launch(void* const* d_in, const int* in_sizes, int n_in,
                              void* d_out, int out_size)
{
    const float* x    = (const float*)d_in[0];
    const float* w_ds = (const float*)d_in[1];
    const float* w_c1 = (const float*)d_in[2];
    const float* w_c2 = (const float*)d_in[3];
    const float* w_c3 = (const float*)d_in[4];
    const float* a_ds = (const float*)d_in[5];
    const float* a_c1 = (const float*)d_in[6];
    const float* a_c2 = (const float*)d_in[7];
    const float* a_c3 = (const float*)d_in[8];
    const float* pegw = (const float*)d_in[9];
    const float* g1   = (const float*)d_in[10];
    const float* b1   = (const float*)d_in[11];
    const float* g2   = (const float*)d_in[12];
    const float* b2   = (const float*)d_in[13];
    const float* g3   = (const float*)d_in[14];
    const float* b3   = (const float*)d_in[15];
    const float* gds  = (const float*)d_in[16];
    const float* bds  = (const float*)d_in[17];
    const float* lds  = (const float*)d_in[18];
    const float* lc1  = (const float*)d_in[19];
    const float* lc2  = (const float*)d_in[20];
    const float* lc3  = (const float*)d_in[21];
    float* out = (float*)d_out;

    Scratch* s = nullptr;
    cudaGetSymbolAddress((void**)&s, g_s);

    // 1) recon: zero accd + redundant minmax + reconstruct + KL partials
    recon_kernel<<<92, 256>>>(w_ds, w_c1, w_c2, w_c3,
                              a_ds, a_c1, a_c2, a_c3,
                              lds, lc1, lc2, lc3);

    // 2) fused ds (y<8, +bnds stats) and c1 (y=8..9) over x — 1000 blocks
    adder1x1_kernel<128, true, false, false><<<dim3(25, 10, 4), 256>>>(
        x, nullptr, nullptr, 0,
        nullptr, nullptr, nullptr, nullptr, nullptr, nullptr);

    // 3) PEG depthwise (512 blocks, half-plane halo staging) + bn1 stats
    peg_stage_kernel<<<512, 256>>>(s->buf_c1, pegw, s->buf_peg,
                                   s->accd + 1152, s->accd + 1216);

    // 4) conv2 3x3 reading peg with inline bn1+relu (+ bn2 stats) — 400 blocks
    adder3x3_kernel<<<dim3(25, 4, 4), 256>>>(
        s->buf_peg, s->f_c2, s->buf_c2,
        s->accd + 1152, s->accd + 1216, g1, b1,
        s->accd + 512, s->accd + 576);

    // 5) conv3 1x1 with inline bn2+relu on input (+ bn3 stats) — 800 blocks
    adder1x1_kernel<64, false, true, true><<<dim3(25, 8, 4), 256>>>(
        s->buf_c2, s->f_c3, s->buf_c3, 256,
        s->accd + 512, s->accd + 576, g2, b2, s->accd + 640, s->accd + 896);

    // 6) fused epilogue: bn3 + relu(bnds) residual + relu, and KL scalar
    final_kernel<<<784, 256>>>(g3, b3, gds, bds, out, out_size);
}

// round 12
// speedup vs baseline: 1.1444x; 1.1444x over previous
#include <cuda_runtime.h>
#include <cuda_bf16.h>

typedef unsigned long long ULL;

#define HW 784
#define NPIX 3136

// ---------------------------------------------------------------------------
// accd layout (doubles): ds_sum@0, ds_ss@256, bn2_sum@512, bn2_ss@576,
// bn3_sum@640, bn3_ss@896, bn1_sum@1152, bn1_ss@1216.
// KL partial slots: kp_*[t*40 + lb]  (blocks per tensor: 32/8/36/16).
// ---------------------------------------------------------------------------
struct __align__(16) Scratch {
    float f_ds[32768], f_c1[8192], f_c2[36864], f_c3[16384];
    float kp_ef[160], kp_el[160], kp_spl[160];
    double accd[1280];
    float buf_ds[802816], buf_c3[802816];
    float buf_c1[200704], buf_peg[200704], buf_c2[200704];
};
__device__ Scratch g_s;

// ---------------- helpers --------------------------------------------------
__device__ __forceinline__ ULL addf2(ULL a, ULL b) {
    ULL r; asm("add.rn.f32x2 %0,%1,%2;" : "=l"(r) : "l"(a), "l"(b)); return r;
}
__device__ __forceinline__ ULL pack2(float v) {
    ULL r; unsigned u = __float_as_uint(v);
    asm("mov.b64 %0,{%1,%1};" : "=l"(r) : "r"(u)); return r;
}
__device__ __forceinline__ ULL packAB(float a, float b) {
    return ((ULL)__float_as_uint(b) << 32) | (ULL)__float_as_uint(a);
}
#define ABS2_MASK 0x7FFFFFFF7FFFFFFFULL

__device__ __forceinline__ float blk_sum(float v) {
    __shared__ float red[8];
    #pragma unroll
    for (int o = 16; o > 0; o >>= 1) v += __shfl_xor_sync(0xffffffffu, v, o);
    int w = threadIdx.x >> 5, l = threadIdx.x & 31;
    if (l == 0) red[w] = v;
    __syncthreads();
    if (w == 0) {
        float s = (l < 8) ? red[l] : 0.f;
        #pragma unroll
        for (int o = 4; o > 0; o >>= 1) s += __shfl_xor_sync(0xffffffffu, s, o);
        if (l == 0) red[0] = s;
    }
    __syncthreads();
    float r = red[0]; __syncthreads();
    return r;
}
__device__ __forceinline__ void blk_minmax(float mn, float mx, float* omn, float* omx) {
    __shared__ float rmn[8], rmx[8];
    #pragma unroll
    for (int o = 16; o > 0; o >>= 1) {
        mn = fminf(mn, __shfl_xor_sync(0xffffffffu, mn, o));
        mx = fmaxf(mx, __shfl_xor_sync(0xffffffffu, mx, o));
    }
    int w = threadIdx.x >> 5, l = threadIdx.x & 31;
    if (l == 0) { rmn[w] = mn; rmx[w] = mx; }
    __syncthreads();
    if (w == 0) {
        float a = (l < 8) ? rmn[l] : 3.4e38f;
        float b = (l < 8) ? rmx[l] : -3.4e38f;
        #pragma unroll
        for (int o = 4; o > 0; o >>= 1) {
            a = fminf(a, __shfl_xor_sync(0xffffffffu, a, o));
            b = fmaxf(b, __shfl_xor_sync(0xffffffffu, b, o));
        }
        if (l == 0) { rmn[0] = a; rmx[0] = b; }
    }
    __syncthreads();
    *omn = rmn[0]; *omx = rmx[0];
    __syncthreads();
}

// ---------------- recon: zero accd + per-tensor minmax + recon + KL parts --
__global__ void __launch_bounds__(256) recon_kernel(
    const float* __restrict__ w0, const float* __restrict__ w1,
    const float* __restrict__ w2, const float* __restrict__ w3,
    const float* __restrict__ a0, const float* __restrict__ a1,
    const float* __restrict__ a2, const float* __restrict__ a3,
    const float* __restrict__ l0, const float* __restrict__ l1,
    const float* __restrict__ l2, const float* __restrict__ l3)
{
    int bid = blockIdx.x, tid = threadIdx.x;
    if (bid == 0) {
        #pragma unroll
        for (int i = 0; i < 5; ++i) g_s.accd[i * 256 + tid] = 0.0;
    }
    int t, lb;
    if (bid < 32)      { t = 0; lb = bid; }
    else if (bid < 40) { t = 1; lb = bid - 32; }
    else if (bid < 76) { t = 2; lb = bid - 40; }
    else               { t = 3; lb = bid - 76; }
    const float *w, *aff, *lap; float* f; int n4;
    if (t == 0)      { w = w0; aff = a0; lap = l0; f = g_s.f_ds; n4 = 8192; }
    else if (t == 1) { w = w1; aff = a1; lap = l1; f = g_s.f_c1; n4 = 2048; }
    else if (t == 2) { w = w2; aff = a2; lap = l2; f = g_s.f_c2; n4 = 9216; }
    else             { w = w3; aff = a3; lap = l3; f = g_s.f_c3; n4 = 4096; }

    float mn = 3.4e38f, mx = -3.4e38f;
    for (int i = tid; i < n4; i += 256) {
        float4 v = ((const float4*)w)[i];
        mn = fminf(mn, fminf(fminf(v.x, v.y), fminf(v.z, v.w)));
        mx = fmaxf(mx, fmaxf(fmaxf(v.x, v.y), fmaxf(v.z, v.w)));
    }
    float wmin, wmax;
    blk_minmax(mn, mx, &wmin, &wmax);
    float range = wmax - wmin;

    int i4 = lb * 256 + tid;
    float4 v4 = ((const float4*)w)[i4];
    float4 l4 = ((const float4*)lap)[i4];
    float vv[4] = {v4.x, v4.y, v4.z, v4.w};
    float ll[4] = {l4.x, l4.y, l4.z, l4.w};
    float fo[4];
    float ef = 0.f, el = 0.f, spl = 0.f;
    #pragma unroll
    for (int k = 0; k < 4; ++k) {
        float v = vv[k];
        float tt = (v - wmin) / range;            // same FP sequence as ref
        int idx = (int)floorf(tt * 100.0f);
        float val = (idx < 100) ? v * aff[idx] : 0.0f;
        fo[k] = val;
        float e = expf(ll[k]);
        ef += expf(val);
        el += e;
        spl += e * (ll[k] - val);
    }
    ((float4*)f)[i4] = make_float4(fo[0], fo[1], fo[2], fo[3]);
    float sef  = blk_sum(ef);
    float sel  = blk_sum(el);
    float sspl = blk_sum(spl);
    if (tid == 0) {
        g_s.kp_ef[t * 40 + lb]  = sef;
        g_s.kp_el[t * 40 + lb]  = sel;
        g_s.kp_spl[t * 40 + lb] = sspl;
    }
}

// ---------------- 1x1 adder: 32px x 8og (og=warp), 4 outs/thread -----------
// FUSED: blockIdx.y<8 -> ds (stats), else c1 (no stats).
template<int CIN, bool FUSED, bool BN_IN, bool STATS_T>
__global__ void __launch_bounds__(256) adder1x1_kernel(
    const float* __restrict__ in, const float* __restrict__ wsrc_a,
    float* __restrict__ out_a, int Cout_a,
    const double* __restrict__ bsum, const double* __restrict__ bss,
    const float* __restrict__ bg, const float* __restrict__ bb,
    double* __restrict__ osum_a, double* __restrict__ oss_a)
{
    __shared__ __align__(16) ULL wq[16 * CIN];   // [og][c][pr(2)]
    __shared__ float scale[CIN], shift[CIN];
    int tid = threadIdx.x;
    int b = blockIdx.z, yb = blockIdx.y;

    const float* wsrc; float* out; int Cout, o0; bool do_stats;
    double *osum, *oss;
    if (FUSED) {
        bool is_ds = yb < 8;
        wsrc = is_ds ? g_s.f_ds : g_s.f_c1;
        out  = is_ds ? g_s.buf_ds : g_s.buf_c1;
        Cout = is_ds ? 256 : 64;
        o0   = (is_ds ? yb : yb - 8) * 32;
        do_stats = is_ds;
        osum = g_s.accd; oss = g_s.accd + 256;
    } else {
        wsrc = wsrc_a; out = out_a; Cout = Cout_a; o0 = yb * 32;
        do_stats = STATS_T; osum = osum_a; oss = oss_a;
    }
    int p0 = blockIdx.x * 32;

    for (int j = tid; j < 16 * CIN; j += 256) {
        int og = j / (2 * CIN), r = j - og * 2 * CIN;
        int c = r >> 1, pr = r & 1;
        int o = o0 + og * 4 + 2 * pr;
        wq[j] = packAB(-wsrc[o * CIN + c], -wsrc[(o + 1) * CIN + c]);
    }
    if (BN_IN) {
        if (tid < CIN) {
            double m = bsum[tid] * (1.0 / 3136.0);
            double var = bss[tid] * (1.0 / 3136.0) - m * m;
            float istd = rsqrtf((float)var + 1e-5f);
            float sc = istd * bg[tid];
            scale[tid] = sc;
            shift[tid] = bb[tid] - (float)m * sc;
        }
    }
    __syncthreads();

    int px = tid & 31, og = tid >> 5;       // og == warp id -> LDS broadcast
    int p = p0 + px;
    bool valid = p < HW;
    int pc = valid ? p : (HW - 1);

    const float* xp = in + (size_t)b * CIN * HW + pc;
    const ULL* wp = wq + og * 2 * CIN;
    ULL acc0 = 0, acc1 = 0;

    #pragma unroll 4
    for (int c = 0; c < CIN; ++c) {
        float xv = xp[(size_t)c * HW];
        if (BN_IN) xv = fmaxf(fmaf(xv, scale[c], shift[c]), 0.0f);
        ULL xx = pack2(xv);
        ulonglong2 ww = *(const ulonglong2*)(wp + c * 2);
        acc0 = addf2(acc0, addf2(xx, ww.x) & ABS2_MASK);
        acc1 = addf2(acc1, addf2(xx, ww.y) & ABS2_MASK);
    }

    float a[4];
    a[0] = __uint_as_float((unsigned)acc0); a[1] = __uint_as_float((unsigned)(acc0 >> 32));
    a[2] = __uint_as_float((unsigned)acc1); a[3] = __uint_as_float((unsigned)(acc1 >> 32));
    int ob = o0 + og * 4;
    if (valid) {
        #pragma unroll
        for (int k = 0; k < 4; ++k)
            out[((size_t)b * Cout + ob + k) * HW + p] = -a[k];
    }
    if (do_stats) {
        #pragma unroll
        for (int k = 0; k < 4; ++k) {
            float s  = valid ? -a[k] : 0.0f;
            float s2 = valid ? a[k] * a[k] : 0.0f;
            #pragma unroll
            for (int o = 16; o > 0; o >>= 1) {
                s  += __shfl_xor_sync(0xffffffffu, s,  o);
                s2 += __shfl_xor_sync(0xffffffffu, s2, o);
            }
            if (px == 0) {
                atomicAdd(&osum[ob + k], (double)s);
                atomicAdd(&oss[ob + k],  (double)s2);
            }
        }
    }
}

// ---------------- PEG depthwise 3x3: smem plane staging + bn1 stats --------
__global__ void __launch_bounds__(256) peg_stage_kernel(
    const float* __restrict__ in, const float* __restrict__ pw,
    float* __restrict__ out, double* __restrict__ osum, double* __restrict__ oss)
{
    __shared__ __align__(16) float plane[NPIX / 4];   // 784 floats
    int tid = threadIdx.x;
    int b = blockIdx.x >> 6, ch = blockIdx.x & 63;
    const float* ip = in + ((size_t)(b * 64 + ch)) * HW;
    float* op = out + ((size_t)(b * 64 + ch)) * HW;

    if (tid < 196) ((float4*)plane)[tid] = ((const float4*)ip)[tid];
    __syncthreads();

    float wc[9];
    #pragma unroll
    for (int t = 0; t < 9; ++t) wc[t] = pw[ch * 9 + t];

    float s = 0.f, s2 = 0.f;
    #pragma unroll
    for (int r = 0; r < 4; ++r) {
        int p = tid + r * 256;
        if (p < HW) {
            int y = p / 28, xx = p - y * 28;
            float acc = 0.f;
            #pragma unroll
            for (int t = 0; t < 9; ++t) {
                int yy = y + t / 3 - 1, xc = xx + t % 3 - 1;
                float v = (yy >= 0 && yy < 28 && xc >= 0 && xc < 28)
                          ? plane[yy * 28 + xc] : 0.0f;
                acc += fabsf(v - wc[t]);
            }
            op[p] = -acc;
            s += -acc;
            s2 += acc * acc;
        }
    }
    s = blk_sum(s); s2 = blk_sum(s2);
    if (tid == 0) {
        atomicAdd(&osum[ch], (double)s);
        atomicAdd(&oss[ch],  (double)s2);
    }
}

// ---------------- 3x3 adder: smem-staged input (bn1 applied once/pixel) ----
// block: 2 output rows (56 px) x 8 outs (og=tid>>6, 2 outs each, warp-uniform)
// grid (14, 8, 4) = 448 blocks. smem: 28KB input tile + 18KB weights.
__global__ void __launch_bounds__(256) adder3x3_kernel(
    const float* __restrict__ in, const float* __restrict__ wsrc,
    const double* __restrict__ bsum, const double* __restrict__ bss,
    const float* __restrict__ bg, const float* __restrict__ bb,
    float* __restrict__ out,
    double* __restrict__ osum, double* __restrict__ oss)
{
    __shared__ __align__(16) float inb[64 * 112];   // 64 ch x 4 rows x 28
    __shared__ __align__(16) ULL wq[4 * 576];       // 4 og x (64c x 9t)
    __shared__ float scale[64], shift[64];
    int tid = threadIdx.x;
    int b = blockIdx.z, o0 = blockIdx.y * 8, y0 = blockIdx.x * 2;

    // bn1 affine (needed before staging)
    if (tid < 64) {
        double m = bsum[tid] * (1.0 / 3136.0);
        double var = bss[tid] * (1.0 / 3136.0) - m * m;
        float istd = rsqrtf((float)var + 1e-5f);
        float sc = istd * bg[tid];
        scale[tid] = sc;
        shift[tid] = bb[tid] - (float)m * sc;
    }
    // weights: wq[og*576 + c*9+t] = pair(outs o0+og*2, o0+og*2+1)
    for (int j = tid; j < 2304; j += 256) {
        int og = j / 576, ct = j - og * 576;
        int o = o0 + og * 2;
        wq[j] = packAB(-wsrc[o * 576 + ct], -wsrc[(o + 1) * 576 + ct]);
    }
    __syncthreads();

    // stage input tile: rows y0-1 .. y0+2 for all 64 channels, bn1+relu once
    for (int j = tid; j < 7168; j += 256) {
        int c = j / 112, r = (j / 28) & 3, xx = j % 28;
        int sy = y0 - 1 + r;
        float v = 0.0f;
        if (sy >= 0 && sy < 28) {
            float raw = in[((size_t)(b * 64 + c)) * HW + sy * 28 + xx];
            v = fmaxf(fmaf(raw, scale[c], shift[c]), 0.0f);
        }
        inb[c * 112 + r * 28 + xx] = v;
    }
    __syncthreads();

    int px = tid & 63, og = tid >> 6;        // og warp-uniform (2 warps/og)
    bool valid = px < 56;
    int pl = valid ? px : 0;
    int yl = pl / 28, x = pl - yl * 28;      // yl 0..1

    const ULL* wp = wq + og * 576;
    ULL acc0 = 0;

    for (int c = 0; c < 64; ++c) {
        const float* base = inb + c * 112 + yl * 28;   // tile row yl+1+dy = base + (dy+1)*28
        const ULL* wc = wp + c * 9;
        #pragma unroll
        for (int dy = 0; dy < 3; ++dy) {
            const float* rowp = base + dy * 28;
            #pragma unroll
            for (int dx = 0; dx < 3; ++dx) {
                int xc = x + dx - 1;
                float v = (xc >= 0 && xc < 28) ? rowp[xc] : 0.0f;
                acc0 = addf2(acc0, addf2(pack2(v), wc[dy * 3 + dx]) & ABS2_MASK);
            }
        }
    }

    float a[2];
    a[0] = __uint_as_float((unsigned)acc0);
    a[1] = __uint_as_float((unsigned)(acc0 >> 32));
    int ob = o0 + og * 2;
    int p = (y0 + yl) * 28 + x;
    if (valid) {
        out[((size_t)b * 64 + ob) * HW + p]     = -a[0];
        out[((size_t)b * 64 + ob + 1) * HW + p] = -a[1];
    }
    #pragma unroll
    for (int k = 0; k < 2; ++k) {
        float s  = valid ? -a[k] : 0.0f;
        float s2 = valid ? a[k] * a[k] : 0.0f;
        #pragma unroll
        for (int o = 16; o > 0; o >>= 1) {
            s  += __shfl_xor_sync(0xffffffffu, s,  o);
            s2 += __shfl_xor_sync(0xffffffffu, s2, o);
        }
        if ((tid & 31) == 0) {
            atomicAdd(&osum[ob + k], (double)s);
            atomicAdd(&oss[ob + k],  (double)s2);
        }
    }
}

// ---------------- final: bn3/bnds + residual + relu + KL -------------------
__global__ void __launch_bounds__(256) final_kernel(
    const float* __restrict__ g3, const float* __restrict__ b3,
    const float* __restrict__ gds, const float* __restrict__ bds,
    float* __restrict__ out, int out_size)
{
    int idx4 = blockIdx.x * 256 + threadIdx.x;
    if (idx4 == 0 && out_size > 802816) {
        const float ns[4] = {32768.f, 8192.f, 36864.f, 16384.f};
        const int nb[4] = {32, 8, 36, 16};
        float kl = 0.f;
        #pragma unroll
        for (int t = 0; t < 4; ++t) {
            float ef = 0.f, el = 0.f, spl = 0.f;
            for (int lb = 0; lb < nb[t]; ++lb) {
                ef  += g_s.kp_ef[t * 40 + lb];
                el  += g_s.kp_el[t * 40 + lb];
                spl += g_s.kp_spl[t * 40 + lb];
            }
            kl += (spl / el + logf(ef) - logf(el)) / ns[t];
        }
        out[802816] = kl;
    }
    size_t base = (size_t)idx4 * 4;
    int ch = (int)((base / HW) & 255);

    double m3d = g_s.accd[640 + ch] * (1.0 / 3136.0);
    double v3d = g_s.accd[896 + ch] * (1.0 / 3136.0) - m3d * m3d;
    float m3 = (float)m3d, istd3 = rsqrtf((float)v3d + 1e-5f);
    float sc3 = istd3 * g3[ch], sh3 = b3[ch] - m3 * sc3;

    double mdd = g_s.accd[0 + ch] * (1.0 / 3136.0);
    double vdd = g_s.accd[256 + ch] * (1.0 / 3136.0) - mdd * mdd;
    float md = (float)mdd, istdd = rsqrtf((float)vdd + 1e-5f);
    float scd = istdd * gds[ch], shd = bds[ch] - md * scd;

    float4 a = *(const float4*)(g_s.buf_c3 + base);
    float4 d = *(const float4*)(g_s.buf_ds + base);
    float4 o;
    o.x = fmaxf(fmaf(a.x, sc3, sh3) + fmaxf(fmaf(d.x, scd, shd), 0.f), 0.f);
    o.y = fmaxf(fmaf(a.y, sc3, sh3) + fmaxf(fmaf(d.y, scd, shd), 0.f), 0.f);
    o.z = fmaxf(fmaf(a.z, sc3, sh3) + fmaxf(fmaf(d.z, scd, shd), 0.f), 0.f);
    o.w = fmaxf(fmaf(a.w, sc3, sh3) + fmaxf(fmaf(d.w, scd, shd), 0.f), 0.f);
    *(float4*)(out + base) = o;
}

// ---------------------------------------------------------------------------
extern "C" void kernel_launch(void* const* d_in, const int* in_sizes, int n_in,
                              void* d_out, int out_size)
{
    const float* x    = (const float*)d_in[0];
    const float* w_ds = (const float*)d_in[1];
    const float* w_c1 = (const float*)d_in[2];
    const float* w_c2 = (const float*)d_in[3];
    const float* w_c3 = (const float*)d_in[4];
    const float* a_ds = (const float*)d_in[5];
    const float* a_c1 = (const float*)d_in[6];
    const float* a_c2 = (const float*)d_in[7];
    const float* a_c3 = (const float*)d_in[8];
    const float* pegw = (const float*)d_in[9];
    const float* g1   = (const float*)d_in[10];
    const float* b1   = (const float*)d_in[11];
    const float* g2   = (const float*)d_in[12];
    const float* b2   = (const float*)d_in[13];
    const float* g3   = (const float*)d_in[14];
    const float* b3   = (const float*)d_in[15];
    const float* gds  = (const float*)d_in[16];
    const float* bds  = (const float*)d_in[17];
    const float* lds  = (const float*)d_in[18];
    const float* lc1  = (const float*)d_in[19];
    const float* lc2  = (const float*)d_in[20];
    const float* lc3  = (const float*)d_in[21];
    float* out = (float*)d_out;

    Scratch* s = nullptr;
    cudaGetSymbolAddress((void**)&s, g_s);

    // 1) recon: zero accd + redundant minmax + reconstruct + KL partials
    recon_kernel<<<92, 256>>>(w_ds, w_c1, w_c2, w_c3,
                              a_ds, a_c1, a_c2, a_c3,
                              lds, lc1, lc2, lc3);

    // 2) fused ds (y<8, +bnds stats) and c1 (y=8..9) over x — 1000 blocks
    adder1x1_kernel<128, true, false, false><<<dim3(25, 10, 4), 256>>>(
        x, nullptr, nullptr, 0,
        nullptr, nullptr, nullptr, nullptr, nullptr, nullptr);

    // 3) PEG depthwise (smem plane staging, 256 blocks) + bn1 stats
    peg_stage_kernel<<<256, 256>>>(s->buf_c1, pegw, s->buf_peg,
                                   s->accd + 1152, s->accd + 1216);

    // 4) conv2 3x3: staged input with bn1+relu applied once/pixel (+bn2 stats)
    adder3x3_kernel<<<dim3(14, 8, 4), 256>>>(
        s->buf_peg, s->f_c2,
        s->accd + 1152, s->accd + 1216, g1, b1,
        s->buf_c2, s->accd + 512, s->accd + 576);

    // 5) conv3 1x1 with inline bn2+relu on input (+ bn3 stats) — 800 blocks
    adder1x1_kernel<64, false, true, true><<<dim3(25, 8, 4), 256>>>(
        s->buf_c2, s->f_c3, s->buf_c3, 256,
        s->accd + 512, s->accd + 576, g2, b2, s->accd + 640, s->accd + 896);

    // 6) fused epilogue: bn3 + relu(bnds) residual + relu, and KL scalar
    final_kernel<<<784, 256>>>(g3, b3, gds, bds, out, out_size);
}

// round 13
// speedup vs baseline: 1.2405x; 1.0839x over previous
#include <cuda_runtime.h>
#include <cuda_bf16.h>

typedef unsigned long long ULL;

#define HW 784
#define NPIX 3136

// ---------------------------------------------------------------------------
// accd layout (doubles): ds_sum@0, ds_ss@256, bn2_sum@512, bn2_ss@576,
// bn3_sum@640, bn3_ss@896, bn1_sum@1152, bn1_ss@1216.
// KL partial slots: kp_*[t*40 + lb]  (blocks per tensor: 32/8/36/16).
// ---------------------------------------------------------------------------
struct __align__(16) Scratch {
    float f_ds[32768], f_c1[8192], f_c2[36864], f_c3[16384];
    float kp_ef[160], kp_el[160], kp_spl[160];
    double accd[1280];
    float buf_ds[802816], buf_c3[802816];
    float buf_c1[200704], buf_peg[200704], buf_c2[200704];
};
__device__ Scratch g_s;

// ---------------- helpers --------------------------------------------------
__device__ __forceinline__ ULL addf2(ULL a, ULL b) {
    ULL r; asm("add.rn.f32x2 %0,%1,%2;" : "=l"(r) : "l"(a), "l"(b)); return r;
}
__device__ __forceinline__ ULL pack2(float v) {
    ULL r; unsigned u = __float_as_uint(v);
    asm("mov.b64 %0,{%1,%1};" : "=l"(r) : "r"(u)); return r;
}
__device__ __forceinline__ ULL packAB(float a, float b) {
    return ((ULL)__float_as_uint(b) << 32) | (ULL)__float_as_uint(a);
}
#define ABS2_MASK 0x7FFFFFFF7FFFFFFFULL

__device__ __forceinline__ float blk_sum(float v) {
    __shared__ float red[8];
    #pragma unroll
    for (int o = 16; o > 0; o >>= 1) v += __shfl_xor_sync(0xffffffffu, v, o);
    int w = threadIdx.x >> 5, l = threadIdx.x & 31;
    if (l == 0) red[w] = v;
    __syncthreads();
    if (w == 0) {
        float s = (l < 8) ? red[l] : 0.f;
        #pragma unroll
        for (int o = 4; o > 0; o >>= 1) s += __shfl_xor_sync(0xffffffffu, s, o);
        if (l == 0) red[0] = s;
    }
    __syncthreads();
    float r = red[0]; __syncthreads();
    return r;
}
__device__ __forceinline__ void blk_minmax(float mn, float mx, float* omn, float* omx) {
    __shared__ float rmn[8], rmx[8];
    #pragma unroll
    for (int o = 16; o > 0; o >>= 1) {
        mn = fminf(mn, __shfl_xor_sync(0xffffffffu, mn, o));
        mx = fmaxf(mx, __shfl_xor_sync(0xffffffffu, mx, o));
    }
    int w = threadIdx.x >> 5, l = threadIdx.x & 31;
    if (l == 0) { rmn[w] = mn; rmx[w] = mx; }
    __syncthreads();
    if (w == 0) {
        float a = (l < 8) ? rmn[l] : 3.4e38f;
        float b = (l < 8) ? rmx[l] : -3.4e38f;
        #pragma unroll
        for (int o = 4; o > 0; o >>= 1) {
            a = fminf(a, __shfl_xor_sync(0xffffffffu, a, o));
            b = fmaxf(b, __shfl_xor_sync(0xffffffffu, b, o));
        }
        if (l == 0) { rmn[0] = a; rmx[0] = b; }
    }
    __syncthreads();
    *omn = rmn[0]; *omx = rmx[0];
    __syncthreads();
}

// ---------------- recon: zero accd + per-tensor minmax + recon + KL parts --
__global__ void __launch_bounds__(256) recon_kernel(
    const float* __restrict__ w0, const float* __restrict__ w1,
    const float* __restrict__ w2, const float* __restrict__ w3,
    const float* __restrict__ a0, const float* __restrict__ a1,
    const float* __restrict__ a2, const float* __restrict__ a3,
    const float* __restrict__ l0, const float* __restrict__ l1,
    const float* __restrict__ l2, const float* __restrict__ l3)
{
    int bid = blockIdx.x, tid = threadIdx.x;
    if (bid == 0) {
        #pragma unroll
        for (int i = 0; i < 5; ++i) g_s.accd[i * 256 + tid] = 0.0;
    }
    int t, lb;
    if (bid < 32)      { t = 0; lb = bid; }
    else if (bid < 40) { t = 1; lb = bid - 32; }
    else if (bid < 76) { t = 2; lb = bid - 40; }
    else               { t = 3; lb = bid - 76; }
    const float *w, *aff, *lap; float* f; int n4;
    if (t == 0)      { w = w0; aff = a0; lap = l0; f = g_s.f_ds; n4 = 8192; }
    else if (t == 1) { w = w1; aff = a1; lap = l1; f = g_s.f_c1; n4 = 2048; }
    else if (t == 2) { w = w2; aff = a2; lap = l2; f = g_s.f_c2; n4 = 9216; }
    else             { w = w3; aff = a3; lap = l3; f = g_s.f_c3; n4 = 4096; }

    float mn = 3.4e38f, mx = -3.4e38f;
    for (int i = tid; i < n4; i += 256) {
        float4 v = ((const float4*)w)[i];
        mn = fminf(mn, fminf(fminf(v.x, v.y), fminf(v.z, v.w)));
        mx = fmaxf(mx, fmaxf(fmaxf(v.x, v.y), fmaxf(v.z, v.w)));
    }
    float wmin, wmax;
    blk_minmax(mn, mx, &wmin, &wmax);
    float range = wmax - wmin;

    int i4 = lb * 256 + tid;
    float4 v4 = ((const float4*)w)[i4];
    float4 l4 = ((const float4*)lap)[i4];
    float vv[4] = {v4.x, v4.y, v4.z, v4.w};
    float ll[4] = {l4.x, l4.y, l4.z, l4.w};
    float fo[4];
    float ef = 0.f, el = 0.f, spl = 0.f;
    #pragma unroll
    for (int k = 0; k < 4; ++k) {
        float v = vv[k];
        float tt = (v - wmin) / range;            // same FP sequence as ref
        int idx = (int)floorf(tt * 100.0f);
        float val = (idx < 100) ? v * aff[idx] : 0.0f;
        fo[k] = val;
        float e = expf(ll[k]);
        ef += expf(val);
        el += e;
        spl += e * (ll[k] - val);
    }
    ((float4*)f)[i4] = make_float4(fo[0], fo[1], fo[2], fo[3]);
    float sef  = blk_sum(ef);
    float sel  = blk_sum(el);
    float sspl = blk_sum(spl);
    if (tid == 0) {
        g_s.kp_ef[t * 40 + lb]  = sef;
        g_s.kp_el[t * 40 + lb]  = sel;
        g_s.kp_spl[t * 40 + lb] = sspl;
    }
}

// ---------------- 1x1 adder: 32px x 8og (og=warp), 4 outs/thread -----------
// FUSED: blockIdx.y<8 -> ds (stats), else c1 (no stats).
template<int CIN, bool FUSED, bool BN_IN, bool STATS_T>
__global__ void __launch_bounds__(256) adder1x1_kernel(
    const float* __restrict__ in, const float* __restrict__ wsrc_a,
    float* __restrict__ out_a, int Cout_a,
    const double* __restrict__ bsum, const double* __restrict__ bss,
    const float* __restrict__ bg, const float* __restrict__ bb,
    double* __restrict__ osum_a, double* __restrict__ oss_a)
{
    __shared__ __align__(16) ULL wq[16 * CIN];   // [og][c][pr(2)]
    __shared__ float scale[CIN], shift[CIN];
    int tid = threadIdx.x;
    int b = blockIdx.z, yb = blockIdx.y;

    const float* wsrc; float* out; int Cout, o0; bool do_stats;
    double *osum, *oss;
    if (FUSED) {
        bool is_ds = yb < 8;
        wsrc = is_ds ? g_s.f_ds : g_s.f_c1;
        out  = is_ds ? g_s.buf_ds : g_s.buf_c1;
        Cout = is_ds ? 256 : 64;
        o0   = (is_ds ? yb : yb - 8) * 32;
        do_stats = is_ds;
        osum = g_s.accd; oss = g_s.accd + 256;
    } else {
        wsrc = wsrc_a; out = out_a; Cout = Cout_a; o0 = yb * 32;
        do_stats = STATS_T; osum = osum_a; oss = oss_a;
    }
    int p0 = blockIdx.x * 32;

    for (int j = tid; j < 16 * CIN; j += 256) {
        int og = j / (2 * CIN), r = j - og * 2 * CIN;
        int c = r >> 1, pr = r & 1;
        int o = o0 + og * 4 + 2 * pr;
        wq[j] = packAB(-wsrc[o * CIN + c], -wsrc[(o + 1) * CIN + c]);
    }
    if (BN_IN) {
        if (tid < CIN) {
            double m = bsum[tid] * (1.0 / 3136.0);
            double var = bss[tid] * (1.0 / 3136.0) - m * m;
            float istd = rsqrtf((float)var + 1e-5f);
            float sc = istd * bg[tid];
            scale[tid] = sc;
            shift[tid] = bb[tid] - (float)m * sc;
        }
    }
    __syncthreads();

    int px = tid & 31, og = tid >> 5;       // og == warp id -> LDS broadcast
    int p = p0 + px;
    bool valid = p < HW;
    int pc = valid ? p : (HW - 1);

    const float* xp = in + (size_t)b * CIN * HW + pc;
    const ULL* wp = wq + og * 2 * CIN;
    ULL acc0 = 0, acc1 = 0;

    #pragma unroll 4
    for (int c = 0; c < CIN; ++c) {
        float xv = xp[(size_t)c * HW];
        if (BN_IN) xv = fmaxf(fmaf(xv, scale[c], shift[c]), 0.0f);
        ULL xx = pack2(xv);
        ulonglong2 ww = *(const ulonglong2*)(wp + c * 2);
        acc0 = addf2(acc0, addf2(xx, ww.x) & ABS2_MASK);
        acc1 = addf2(acc1, addf2(xx, ww.y) & ABS2_MASK);
    }

    float a[4];
    a[0] = __uint_as_float((unsigned)acc0); a[1] = __uint_as_float((unsigned)(acc0 >> 32));
    a[2] = __uint_as_float((unsigned)acc1); a[3] = __uint_as_float((unsigned)(acc1 >> 32));
    int ob = o0 + og * 4;
    if (valid) {
        #pragma unroll
        for (int k = 0; k < 4; ++k)
            out[((size_t)b * Cout + ob + k) * HW + p] = -a[k];
    }
    if (do_stats) {
        #pragma unroll
        for (int k = 0; k < 4; ++k) {
            float s  = valid ? -a[k] : 0.0f;
            float s2 = valid ? a[k] * a[k] : 0.0f;
            #pragma unroll
            for (int o = 16; o > 0; o >>= 1) {
                s  += __shfl_xor_sync(0xffffffffu, s,  o);
                s2 += __shfl_xor_sync(0xffffffffu, s2, o);
            }
            if (px == 0) {
                atomicAdd(&osum[ob + k], (double)s);
                atomicAdd(&oss[ob + k],  (double)s2);
            }
        }
    }
}

// ---------------- PEG depthwise 3x3: smem plane staging + bn1 stats --------
__global__ void __launch_bounds__(256) peg_stage_kernel(
    const float* __restrict__ in, const float* __restrict__ pw,
    float* __restrict__ out, double* __restrict__ osum, double* __restrict__ oss)
{
    __shared__ __align__(16) float plane[NPIX / 4];   // 784 floats
    int tid = threadIdx.x;
    int b = blockIdx.x >> 6, ch = blockIdx.x & 63;
    const float* ip = in + ((size_t)(b * 64 + ch)) * HW;
    float* op = out + ((size_t)(b * 64 + ch)) * HW;

    if (tid < 196) ((float4*)plane)[tid] = ((const float4*)ip)[tid];
    __syncthreads();

    float wc[9];
    #pragma unroll
    for (int t = 0; t < 9; ++t) wc[t] = pw[ch * 9 + t];

    float s = 0.f, s2 = 0.f;
    #pragma unroll
    for (int r = 0; r < 4; ++r) {
        int p = tid + r * 256;
        if (p < HW) {
            int y = p / 28, xx = p - y * 28;
            float acc = 0.f;
            #pragma unroll
            for (int t = 0; t < 9; ++t) {
                int yy = y + t / 3 - 1, xc = xx + t % 3 - 1;
                float v = (yy >= 0 && yy < 28 && xc >= 0 && xc < 28)
                          ? plane[yy * 28 + xc] : 0.0f;
                acc += fabsf(v - wc[t]);
            }
            op[p] = -acc;
            s += -acc;
            s2 += acc * acc;
        }
    }
    s = blk_sum(s); s2 = blk_sum(s2);
    if (tid == 0) {
        atomicAdd(&osum[ch], (double)s);
        atomicAdd(&oss[ch],  (double)s2);
    }
}

// ---------------- 3x3 adder: padded smem tile, no inner-loop guards --------
// block: 2 output rows (56 px) x 8 outs (og=tid>>6); grid (14, 8, 4) = 448.
// smem tile: 64 ch x 4 rows x 32 cols (stride 32; col s <-> x = s-1; borders 0)
__global__ void __launch_bounds__(256) adder3x3_kernel(
    const float* __restrict__ in, const float* __restrict__ wsrc,
    const double* __restrict__ bsum, const double* __restrict__ bss,
    const float* __restrict__ bg, const float* __restrict__ bb,
    float* __restrict__ out,
    double* __restrict__ osum, double* __restrict__ oss)
{
    __shared__ __align__(16) float inb[64 * 128];   // 32 KB
    __shared__ __align__(16) ULL wq[4 * 576];       // 18 KB
    __shared__ float scale[64], shift[64];
    int tid = threadIdx.x;
    int b = blockIdx.z, o0 = blockIdx.y * 8, y0 = blockIdx.x * 2;

    if (tid < 64) {
        double m = bsum[tid] * (1.0 / 3136.0);
        double var = bss[tid] * (1.0 / 3136.0) - m * m;
        float istd = rsqrtf((float)var + 1e-5f);
        float sc = istd * bg[tid];
        scale[tid] = sc;
        shift[tid] = bb[tid] - (float)m * sc;
    }
    for (int j = tid; j < 2304; j += 256) {
        int og = j / 576, ct = j - og * 576;
        int o = o0 + og * 2;
        wq[j] = packAB(-wsrc[o * 576 + ct], -wsrc[(o + 1) * 576 + ct]);
    }
    __syncthreads();

    // stage padded tile: j = c<<7 | r<<5 | s; bn1+relu applied once per pixel
    for (int j = tid; j < 8192; j += 256) {
        int c = j >> 7, r = (j >> 5) & 3, sgn = j & 31;
        int sy = y0 - 1 + r, ox = sgn - 1;
        float v = 0.0f;
        if (sy >= 0 && sy < 28 && ox >= 0 && ox < 28) {
            float raw = in[((size_t)(b * 64 + c)) * HW + sy * 28 + ox];
            v = fmaxf(fmaf(raw, scale[c], shift[c]), 0.0f);
        }
        inb[j] = v;
    }
    __syncthreads();

    int px = tid & 63, og = tid >> 6;        // og warp-uniform (2 warps/og)
    bool valid = px < 56;
    int pl = valid ? px : 0;
    int yl = pl / 28, x = pl - yl * 28;      // yl 0..1

    const ULL* wp = wq + og * 576;
    const float* tb = inb + yl * 32 + x;     // tap (dy,dx) at tb[c*128 + dy*32 + dx]
    ULL acc0 = 0;

    for (int c = 0; c < 64; ++c) {
        const float* rp = tb + c * 128;
        const ULL* wc = wp + c * 9;
        #pragma unroll
        for (int dy = 0; dy < 3; ++dy) {
            #pragma unroll
            for (int dx = 0; dx < 3; ++dx) {
                float v = rp[dy * 32 + dx];
                acc0 = addf2(acc0, addf2(pack2(v), wc[dy * 3 + dx]) & ABS2_MASK);
            }
        }
    }

    float a[2];
    a[0] = __uint_as_float((unsigned)acc0);
    a[1] = __uint_as_float((unsigned)(acc0 >> 32));
    int ob = o0 + og * 2;
    int p = (y0 + yl) * 28 + x;
    if (valid) {
        out[((size_t)b * 64 + ob) * HW + p]     = -a[0];
        out[((size_t)b * 64 + ob + 1) * HW + p] = -a[1];
    }
    #pragma unroll
    for (int k = 0; k < 2; ++k) {
        float s  = valid ? -a[k] : 0.0f;
        float s2 = valid ? a[k] * a[k] : 0.0f;
        #pragma unroll
        for (int o = 16; o > 0; o >>= 1) {
            s  += __shfl_xor_sync(0xffffffffu, s,  o);
            s2 += __shfl_xor_sync(0xffffffffu, s2, o);
        }
        if ((tid & 31) == 0) {
            atomicAdd(&osum[ob + k], (double)s);
            atomicAdd(&oss[ob + k],  (double)s2);
        }
    }
}

// ---------------- final: bn3/bnds (smem LUT) + residual + relu + KL --------
__global__ void __launch_bounds__(256) final_kernel(
    const float* __restrict__ g3, const float* __restrict__ b3,
    const float* __restrict__ gds, const float* __restrict__ bds,
    float* __restrict__ out, int out_size)
{
    __shared__ float4 lut3[3], lutd[3];   // {sc3,sh3}/{scd,shd} per plane
    int B = blockIdx.x, tid = threadIdx.x;
    int p_lo = (B * 256) / 196;           // first plane touched by this block

    if (tid < 3) {
        int plane = p_lo + tid;
        if (plane < 1024) {
            int ch = plane & 255;
            double m3d = g_s.accd[640 + ch] * (1.0 / 3136.0);
            double v3d = g_s.accd[896 + ch] * (1.0 / 3136.0) - m3d * m3d;
            float m3 = (float)m3d, istd3 = rsqrtf((float)v3d + 1e-5f);
            float sc3 = istd3 * g3[ch];
            double mdd = g_s.accd[0 + ch] * (1.0 / 3136.0);
            double vdd = g_s.accd[256 + ch] * (1.0 / 3136.0) - mdd * mdd;
            float md = (float)mdd, istdd = rsqrtf((float)vdd + 1e-5f);
            float scd = istdd * gds[ch];
            lut3[tid] = make_float4(sc3, b3[ch] - m3 * sc3, 0.f, 0.f);
            lutd[tid] = make_float4(scd, bds[ch] - md * scd, 0.f, 0.f);
        }
    }
    __syncthreads();

    int idx4 = B * 256 + tid;
    if (idx4 == 0 && out_size > 802816) {
        const float ns[4] = {32768.f, 8192.f, 36864.f, 16384.f};
        const int nb[4] = {32, 8, 36, 16};
        float kl = 0.f;
        #pragma unroll
        for (int t = 0; t < 4; ++t) {
            float ef = 0.f, el = 0.f, spl = 0.f;
            for (int lb = 0; lb < nb[t]; ++lb) {
                ef  += g_s.kp_ef[t * 40 + lb];
                el  += g_s.kp_el[t * 40 + lb];
                spl += g_s.kp_spl[t * 40 + lb];
            }
            kl += (spl / el + logf(ef) - logf(el)) / ns[t];
        }
        out[802816] = kl;
    }

    int plane = idx4 / 196;
    int li = plane - p_lo;
    float4 L3 = lut3[li], Ld = lutd[li];
    float sc3 = L3.x, sh3 = L3.y, scd = Ld.x, shd = Ld.y;

    size_t base = (size_t)idx4 * 4;
    float4 a = *(const float4*)(g_s.buf_c3 + base);
    float4 d = *(const float4*)(g_s.buf_ds + base);
    float4 o;
    o.x = fmaxf(fmaf(a.x, sc3, sh3) + fmaxf(fmaf(d.x, scd, shd), 0.f), 0.f);
    o.y = fmaxf(fmaf(a.y, sc3, sh3) + fmaxf(fmaf(d.y, scd, shd), 0.f), 0.f);
    o.z = fmaxf(fmaf(a.z, sc3, sh3) + fmaxf(fmaf(d.z, scd, shd), 0.f), 0.f);
    o.w = fmaxf(fmaf(a.w, sc3, sh3) + fmaxf(fmaf(d.w, scd, shd), 0.f), 0.f);
    *(float4*)(out + base) = o;
}

// ---------------------------------------------------------------------------
extern "C" void kernel_launch(void* const* d_in, const int* in_sizes, int n_in,
                              void* d_out, int out_size)
{
    const float* x    = (const float*)d_in[0];
    const float* w_ds = (const float*)d_in[1];
    const float* w_c1 = (const float*)d_in[2];
    const float* w_c2 = (const float*)d_in[3];
    const float* w_c3 = (const float*)d_in[4];
    const float* a_ds = (const float*)d_in[5];
    const float* a_c1 = (const float*)d_in[6];
    const float* a_c2 = (const float*)d_in[7];
    const float* a_c3 = (const float*)d_in[8];
    const float* pegw = (const float*)d_in[9];
    const float* g1   = (const float*)d_in[10];
    const float* b1   = (const float*)d_in[11];
    const float* g2   = (const float*)d_in[12];
    const float* b2   = (const float*)d_in[13];
    const float* g3   = (const float*)d_in[14];
    const float* b3   = (const float*)d_in[15];
    const float* gds  = (const float*)d_in[16];
    const float* bds  = (const float*)d_in[17];
    const float* lds  = (const float*)d_in[18];
    const float* lc1  = (const float*)d_in[19];
    const float* lc2  = (const float*)d_in[20];
    const float* lc3  = (const float*)d_in[21];
    float* out = (float*)d_out;

    Scratch* s = nullptr;
    cudaGetSymbolAddress((void**)&s, g_s);

    // 1) recon: zero accd + redundant minmax + reconstruct + KL partials
    recon_kernel<<<92, 256>>>(w_ds, w_c1, w_c2, w_c3,
                              a_ds, a_c1, a_c2, a_c3,
                              lds, lc1, lc2, lc3);

    // 2) fused ds (y<8, +bnds stats) and c1 (y=8..9) over x — 1000 blocks
    adder1x1_kernel<128, true, false, false><<<dim3(25, 10, 4), 256>>>(
        x, nullptr, nullptr, 0,
        nullptr, nullptr, nullptr, nullptr, nullptr, nullptr);

    // 3) PEG depthwise (smem plane staging, 256 blocks) + bn1 stats
    peg_stage_kernel<<<256, 256>>>(s->buf_c1, pegw, s->buf_peg,
                                   s->accd + 1152, s->accd + 1216);

    // 4) conv2 3x3: padded staged tile, bn1+relu once/pixel (+bn2 stats)
    adder3x3_kernel<<<dim3(14, 8, 4), 256>>>(
        s->buf_peg, s->f_c2,
        s->accd + 1152, s->accd + 1216, g1, b1,
        s->buf_c2, s->accd + 512, s->accd + 576);

    // 5) conv3 1x1 with inline bn2+relu on input (+ bn3 stats) — 800 blocks
    adder1x1_kernel<64, false, true, true><<<dim3(25, 8, 4), 256>>>(
        s->buf_c2, s->f_c3, s->buf_c3, 256,
        s->accd + 512, s->accd + 576, g2, b2, s->accd + 640, s->accd + 896);

    // 6) fused epilogue: bn3 + relu(bnds) residual + relu, and KL scalar
    final_kernel<<<784, 256>>>(g3, b3, gds, bds, out, out_size);
}